// round 11
// baseline (speedup 1.0000x reference)
#include <cuda_runtime.h>
#include <math.h>
#include <stdint.h>

#define Bb 128
#define Ss 1024
#define Dd 512
#define Nn 784

#define NSPLIT 2
#define COLS_PER (Nn / NSPLIT)   // 392
#define NFULL 24                 // full 16-col tiles per half (384 cols) + 8-col tail
#define ATHREADS 256             // 8 warps; warp w owns d-rows [64w, 64w+64)
#define KSPLIT 32                // q-GEMM split-K factor
#define USPLIT 16                // u split factor

// ---------------- scratch (no allocations allowed) ----------------
__device__ float g_qpart[KSPLIT * Bb * Dd];    // q split-K partials (8 MB)
__device__ float g_upart[USPLIT * 2 * Dd];     // u partials
__device__ float g_pacc[NSPLIT * Bb * Dd];     // unnormalized pooled partials
__device__ float g_mz[NSPLIT * Bb * 2];        // per-half (m, Z)

// ================= K1: heterogeneous prep =================
// CTA [0,512):    q split-K partials, 64x64 tile, 4x4 blocking, 2 k-iters
// CTA [512,576):  u partials (USPLIT=16, 32 d-rows each)
// CTA [576,1088): out bias init
__global__ void prep_kernel(const float* __restrict__ in_state,  // [B,S]
                            const float* __restrict__ Wq,        // [D,S]
                            const float* __restrict__ Wa,        // [D]
                            const float* __restrict__ Wc,        // [D,2D]
                            const float* __restrict__ bo,        // [S]
                            float* __restrict__ out,             // [B,S]
                            float* __restrict__ qpart,
                            float* __restrict__ upart) {
    const int cta = blockIdx.x;
    const int tid = threadIdx.x;  // 256 threads

    if (cta < 512) {
        __shared__ float As[16][72];
        __shared__ float Bs[16][72];
        const int z  = cta >> 4;           // 0..31
        const int g  = cta & 15;
        const int gx = g & 7;
        const int gy = g >> 3;
        const int tx = tid & 15, ty = tid >> 4;
        const int row0 = gy * 64, col0 = gx * 64;
        const int kbeg = z * (Ss / KSPLIT);   // 32 k per slice
        const int lm = tid >> 2;
        const int lk = (tid & 3) * 4;
        float a00=0,a01=0,a02=0,a03=0, a10=0,a11=0,a12=0,a13=0;
        float a20=0,a21=0,a22=0,a23=0, a30=0,a31=0,a32=0,a33=0;

        for (int kb = kbeg; kb < kbeg + Ss / KSPLIT; kb += 16) {
            float4 av = *(const float4*)&in_state[(size_t)(row0 + lm) * Ss + kb + lk];
            float4 bv = *(const float4*)&Wq[(size_t)(col0 + lm) * Ss + kb + lk];
            As[lk + 0][lm] = av.x; As[lk + 1][lm] = av.y;
            As[lk + 2][lm] = av.z; As[lk + 3][lm] = av.w;
            Bs[lk + 0][lm] = bv.x; Bs[lk + 1][lm] = bv.y;
            Bs[lk + 2][lm] = bv.z; Bs[lk + 3][lm] = bv.w;
            __syncthreads();
#pragma unroll
            for (int kk = 0; kk < 16; kk++) {
                float4 a4 = *(float4*)&As[kk][ty * 4];
                float4 b4 = *(float4*)&Bs[kk][tx * 4];
                a00 += a4.x*b4.x; a01 += a4.x*b4.y; a02 += a4.x*b4.z; a03 += a4.x*b4.w;
                a10 += a4.y*b4.x; a11 += a4.y*b4.y; a12 += a4.y*b4.z; a13 += a4.y*b4.w;
                a20 += a4.z*b4.x; a21 += a4.z*b4.y; a22 += a4.z*b4.z; a23 += a4.z*b4.w;
                a30 += a4.w*b4.x; a31 += a4.w*b4.y; a32 += a4.w*b4.z; a33 += a4.w*b4.w;
            }
            __syncthreads();
        }
        float* base = qpart + (size_t)z * Bb * Dd + (size_t)(row0 + ty * 4) * Dd + col0 + tx * 4;
        *(float4*)(base + 0 * Dd) = make_float4(a00, a01, a02, a03);
        *(float4*)(base + 1 * Dd) = make_float4(a10, a11, a12, a13);
        *(float4*)(base + 2 * Dd) = make_float4(a20, a21, a22, a23);
        *(float4*)(base + 3 * Dd) = make_float4(a30, a31, a32, a33);
    } else if (cta < 576) {
        const int local = cta - 512;       // 0..63
        const int colchunk = local & 3;    // 256 cols each
        const int kchunk = local >> 2;     // 0..15, 32 d-rows each
        const int col = colchunk * 256 + tid;
        const int dbeg = kchunk * 32;
        float acc = 0.f;
#pragma unroll
        for (int d = dbeg; d < dbeg + 32; d++)
            acc += Wa[d] * Wc[(size_t)d * (2 * Dd) + col];
        upart[kchunk * (2 * Dd) + col] = acc;
    } else {
        const int j = (cta - 576) * 256 + tid;  // 512*256 = 131072 exactly
        out[j] = bo[j & (Ss - 1)];
    }
}

// ================= K2: flash attention, n-split halves, 2 CTAs/SM (R10-proven) ==========
__global__ __launch_bounds__(ATHREADS, 2) void attn_flash(
    const float* __restrict__ image, const float* __restrict__ qpart,
    const float* __restrict__ upart, const float* __restrict__ bq,
    float* __restrict__ pacc, float* __restrict__ mz) {
    __shared__ float spart[2][192];   // 8 warp-rows, stride 20, + pad

    const int b = blockIdx.x >> 1;
    const int c = blockIdx.x & 1;
    const int lane = threadIdx.x & 31;
    const int warp = threadIdx.x >> 5;   // 0..7
    const int d0 = warp * 64;
    const int r = lane >> 2;             // 0..7
    const int k = lane & 3;              // 0..3
    const float* imgb = image + (size_t)b * Dd * Nn + (size_t)c * COLS_PER;
    const float4* p0 = reinterpret_cast<const float4*>(imgb + (size_t)(d0 + r) * Nn) + k;

    // ---- prologue: fused logit weights ----
    const int dg0 = d0 + lane, dg1 = d0 + 32 + lane;
    float q0 = 0.f, q1 = 0.f, u10 = 0.f, u11 = 0.f, u20 = 0.f, u21 = 0.f;
#pragma unroll
    for (int p = 0; p < KSPLIT; p++) {
        q0 += qpart[((size_t)p * Bb + b) * Dd + dg0];
        q1 += qpart[((size_t)p * Bb + b) * Dd + dg1];
    }
#pragma unroll
    for (int p = 0; p < USPLIT; p++) {
        u10 += upart[p * (2 * Dd) + dg0];
        u11 += upart[p * (2 * Dd) + dg1];
        u20 += upart[p * (2 * Dd) + Dd + dg0];
        u21 += upart[p * (2 * Dd) + Dd + dg1];
    }
    const float swv0 = u10 * (q0 + bq[dg0]) + u20;
    const float swv1 = u11 * (q1 + bq[dg1]) + u21;

    float4 ra[8], rb[8], acc[8];
#pragma unroll
    for (int j = 0; j < 8; j++) acc[j] = make_float4(0.f, 0.f, 0.f, 0.f);
    float m = -INFINITY, Zl = 0.f;

#define LOADF(T, REG)                                                              \
    {                                                                              \
        _Pragma("unroll")                                                          \
        for (int j = 0; j < 8; j++) REG[j] = __ldg(&p0[(size_t)j * 1568 + (T) * 4]);\
    }
#define LOADT(REG)                                                                 \
    {                                                                              \
        _Pragma("unroll")                                                          \
        for (int j = 0; j < 8; j++)                                                \
            REG[j] = (k < 2) ? __ldg(&p0[(size_t)j * 1568 + 96])                   \
                             : make_float4(0.f, 0.f, 0.f, 0.f);                    \
    }

#define PROC(REG, PAR, TAILF)                                                      \
    {                                                                              \
        float4 s4 = make_float4(0.f, 0.f, 0.f, 0.f);                               \
        _Pragma("unroll")                                                          \
        for (int j = 0; j < 4; j++) {                                              \
            float wj = __shfl_sync(0xffffffffu, swv0, 8 * j + r);                  \
            s4.x += wj * REG[j].x; s4.y += wj * REG[j].y;                          \
            s4.z += wj * REG[j].z; s4.w += wj * REG[j].w;                          \
        }                                                                          \
        _Pragma("unroll")                                                          \
        for (int j = 4; j < 8; j++) {                                              \
            float wj = __shfl_sync(0xffffffffu, swv1, 8 * (j - 4) + r);            \
            s4.x += wj * REG[j].x; s4.y += wj * REG[j].y;                          \
            s4.z += wj * REG[j].z; s4.w += wj * REG[j].w;                          \
        }                                                                          \
        _Pragma("unroll")                                                          \
        for (int o = 4; o <= 16; o <<= 1) {                                        \
            s4.x += __shfl_xor_sync(0xffffffffu, s4.x, o);                         \
            s4.y += __shfl_xor_sync(0xffffffffu, s4.y, o);                         \
            s4.z += __shfl_xor_sync(0xffffffffu, s4.z, o);                         \
            s4.w += __shfl_xor_sync(0xffffffffu, s4.w, o);                         \
        }                                                                          \
        if (lane < 4) *(float4*)&spart[PAR][warp * 20 + lane * 4] = s4;            \
        __syncthreads();                                                           \
        float v = 0.f;                                                             \
        _Pragma("unroll")                                                          \
        for (int rr = 0; rr < 8; rr++) v += spart[PAR][rr * 20 + lane];            \
        const bool actv = (TAILF) ? (lane < 8) : (lane < 16);                      \
        float vm = actv ? v : -INFINITY;                                           \
        _Pragma("unroll")                                                          \
        for (int o = 16; o; o >>= 1)                                               \
            vm = fmaxf(vm, __shfl_xor_sync(0xffffffffu, vm, o));                   \
        float newm = fmaxf(m, vm);                                                 \
        float e = actv ? __expf(v - newm) : 0.f;                                   \
        float ts = e;                                                              \
        _Pragma("unroll")                                                          \
        for (int o = 16; o; o >>= 1) ts += __shfl_xor_sync(0xffffffffu, ts, o);    \
        const bool resc = (newm > m);                                              \
        float sc = resc ? __expf(m - newm) : 1.f;                                  \
        Zl = Zl * sc + ts;                                                         \
        m = newm;                                                                  \
        float4 e4;                                                                 \
        e4.x = __shfl_sync(0xffffffffu, e, 4 * k);                                 \
        e4.y = __shfl_sync(0xffffffffu, e, 4 * k + 1);                             \
        e4.z = __shfl_sync(0xffffffffu, e, 4 * k + 2);                             \
        e4.w = __shfl_sync(0xffffffffu, e, 4 * k + 3);                             \
        if (resc) {                                                                \
            _Pragma("unroll")                                                      \
            for (int j = 0; j < 8; j++) {                                          \
                acc[j].x = acc[j].x * sc + e4.x * REG[j].x;                        \
                acc[j].y = acc[j].y * sc + e4.y * REG[j].y;                        \
                acc[j].z = acc[j].z * sc + e4.z * REG[j].z;                        \
                acc[j].w = acc[j].w * sc + e4.w * REG[j].w;                        \
            }                                                                      \
        } else {                                                                   \
            _Pragma("unroll")                                                      \
            for (int j = 0; j < 8; j++) {                                          \
                acc[j].x += e4.x * REG[j].x;                                       \
                acc[j].y += e4.y * REG[j].y;                                       \
                acc[j].z += e4.z * REG[j].z;                                       \
                acc[j].w += e4.w * REG[j].w;                                       \
            }                                                                      \
        }                                                                          \
    }

    LOADF(0, ra)
    for (int t = 0; t < NFULL; t += 2) {
        LOADF(t + 1, rb)
        PROC(ra, 0, false)
        if (t + 2 < NFULL) { LOADF(t + 2, ra) } else { LOADT(ra) }
        PROC(rb, 1, false)
    }
    PROC(ra, 0, true)
#undef LOADF
#undef LOADT
#undef PROC

#pragma unroll
    for (int j = 0; j < 8; j++) {
        float h = acc[j].x + acc[j].y + acc[j].z + acc[j].w;
        h += __shfl_xor_sync(0xffffffffu, h, 1);
        h += __shfl_xor_sync(0xffffffffu, h, 2);
        if (k == 0) pacc[((size_t)c * Bb + b) * Dd + d0 + 8 * j + r] = h;
    }
    if (warp == 0 && lane == 0) {
        mz[(c * Bb + b) * 2 + 0] = m;
        mz[(c * Bb + b) * 2 + 1] = Zl;
    }
}

// ================= K3: out += combine(pacc) @ Wo^T, split-K x16, fused softmax merge ====
// A[b][k] = f0[b]*pacc0[b][k] + f1[b]*pacc1[b][k], f computed per-row from (m,Z).
__global__ void gemm_out(const float* __restrict__ pacc,  // [2][B][D]
                         const float* __restrict__ mz,    // [2][B][2]
                         const float* __restrict__ Bm,    // Wo [S,D]
                         float* __restrict__ C) {         // out [B,S] (bias pre-set)
    __shared__ float As[16][72];
    __shared__ float Bs[16][72];
    __shared__ float sf0[64], sf1[64];
    const int tid = threadIdx.x;
    const int gx = blockIdx.x;         // 16 col tiles
    const int gy = blockIdx.y;         // 2 row tiles
    const int z  = blockIdx.z;         // 16 k slices
    const int tx = tid & 15, ty = tid >> 4;
    const int row0 = gy * 64, col0 = gx * 64;
    const int kbeg = z * (Dd / 16);    // 32 k per slice
    const int lm = tid >> 2;
    const int lk = (tid & 3) * 4;

    // per-row merge factors
    if (tid < 64) {
        const int b = row0 + tid;
        const float m1 = mz[(0 * Bb + b) * 2 + 0], z1 = mz[(0 * Bb + b) * 2 + 1];
        const float m2 = mz[(1 * Bb + b) * 2 + 0], z2 = mz[(1 * Bb + b) * 2 + 1];
        const float M = fmaxf(m1, m2);
        const float e1 = __expf(m1 - M), e2 = __expf(m2 - M);
        const float inv = 1.f / (z1 * e1 + z2 * e2);
        sf0[tid] = e1 * inv;
        sf1[tid] = e2 * inv;
    }
    __syncthreads();

    float a00=0,a01=0,a02=0,a03=0, a10=0,a11=0,a12=0,a13=0;
    float a20=0,a21=0,a22=0,a23=0, a30=0,a31=0,a32=0,a33=0;

    for (int kb = kbeg; kb < kbeg + Dd / 16; kb += 16) {
        const float f0 = sf0[lm], f1 = sf1[lm];
        float4 p0v = *(const float4*)&pacc[(size_t)(0 * Bb + row0 + lm) * Dd + kb + lk];
        float4 p1v = *(const float4*)&pacc[(size_t)(1 * Bb + row0 + lm) * Dd + kb + lk];
        float4 av = make_float4(f0 * p0v.x + f1 * p1v.x, f0 * p0v.y + f1 * p1v.y,
                                f0 * p0v.z + f1 * p1v.z, f0 * p0v.w + f1 * p1v.w);
        float4 bv = *(const float4*)&Bm[(size_t)(col0 + lm) * Dd + kb + lk];
        As[lk + 0][lm] = av.x; As[lk + 1][lm] = av.y;
        As[lk + 2][lm] = av.z; As[lk + 3][lm] = av.w;
        Bs[lk + 0][lm] = bv.x; Bs[lk + 1][lm] = bv.y;
        Bs[lk + 2][lm] = bv.z; Bs[lk + 3][lm] = bv.w;
        __syncthreads();
#pragma unroll
        for (int kk = 0; kk < 16; kk++) {
            float4 a4 = *(float4*)&As[kk][ty * 4];
            float4 b4 = *(float4*)&Bs[kk][tx * 4];
            a00 += a4.x*b4.x; a01 += a4.x*b4.y; a02 += a4.x*b4.z; a03 += a4.x*b4.w;
            a10 += a4.y*b4.x; a11 += a4.y*b4.y; a12 += a4.y*b4.z; a13 += a4.y*b4.w;
            a20 += a4.z*b4.x; a21 += a4.z*b4.y; a22 += a4.z*b4.z; a23 += a4.z*b4.w;
            a30 += a4.w*b4.x; a31 += a4.w*b4.y; a32 += a4.w*b4.z; a33 += a4.w*b4.w;
        }
        __syncthreads();
    }
    float* base = C + (size_t)(row0 + ty * 4) * Ss + col0 + tx * 4;
    atomicAdd(base + 0 * Ss + 0, a00); atomicAdd(base + 0 * Ss + 1, a01);
    atomicAdd(base + 0 * Ss + 2, a02); atomicAdd(base + 0 * Ss + 3, a03);
    atomicAdd(base + 1 * Ss + 0, a10); atomicAdd(base + 1 * Ss + 1, a11);
    atomicAdd(base + 1 * Ss + 2, a12); atomicAdd(base + 1 * Ss + 3, a13);
    atomicAdd(base + 2 * Ss + 0, a20); atomicAdd(base + 2 * Ss + 1, a21);
    atomicAdd(base + 2 * Ss + 2, a22); atomicAdd(base + 2 * Ss + 3, a23);
    atomicAdd(base + 3 * Ss + 0, a30); atomicAdd(base + 3 * Ss + 1, a31);
    atomicAdd(base + 3 * Ss + 2, a32); atomicAdd(base + 3 * Ss + 3, a33);
}

// ---------------- launcher (3 graph nodes) ----------------
extern "C" void kernel_launch(void* const* d_in, const int* in_sizes, int n_in,
                              void* d_out, int out_size) {
    const float* in_state = (const float*)d_in[0];  // [B, S]
    const float* image    = (const float*)d_in[1];  // [B, D, N]
    const float* Wq       = (const float*)d_in[2];  // [D, S]
    const float* bq       = (const float*)d_in[3];  // [D]
    const float* Wc       = (const float*)d_in[4];  // [D, 2D]
    // d_in[5] = bc (cancels in softmax)
    const float* Wa       = (const float*)d_in[6];  // [1, D]
    // d_in[7] = ba (cancels in softmax)
    const float* Wo       = (const float*)d_in[8];  // [S, D]
    const float* bo       = (const float*)d_in[9];  // [S]
    float* out = (float*)d_out;                     // [B, S]

    float* qpart_ptr;  cudaGetSymbolAddress((void**)&qpart_ptr, g_qpart);
    float* upart_ptr;  cudaGetSymbolAddress((void**)&upart_ptr, g_upart);
    float* pacc_ptr;   cudaGetSymbolAddress((void**)&pacc_ptr, g_pacc);
    float* mz_ptr;     cudaGetSymbolAddress((void**)&mz_ptr, g_mz);

    // K1: q-partials (splitk32) + u-partials (usplit16) + out-bias
    prep_kernel<<<1088, 256>>>(in_state, Wq, Wa, Wc, bo, out, qpart_ptr, upart_ptr);

    // K2: flash attention over column halves (256 co-resident CTAs)
    attn_flash<<<Bb * NSPLIT, ATHREADS>>>(image, qpart_ptr, upart_ptr, bq, pacc_ptr, mz_ptr);

    // K3: out += merge(pacc) @ Wo^T (split-K x16, combine fused into A-load)
    {
        dim3 grid(16, 2, 16);
        gemm_out<<<grid, 256>>>(pacc_ptr, mz_ptr, Wo, out);
    }
}

// round 12
// speedup vs baseline: 1.0270x; 1.0270x over previous
#include <cuda_runtime.h>
#include <math.h>
#include <stdint.h>

#define Bb 128
#define Ss 1024
#define Dd 512
#define Nn 784

#define NSPLIT 2
#define COLS_PER (Nn / NSPLIT)   // 392
#define NFULL 24                 // full 16-col tiles per half (384 cols) + 8-col tail
#define ATHREADS 256             // 8 warps; warp w owns d-rows [64w, 64w+64)
#define KSPLIT 32                // q-GEMM split-K factor
#define USPLIT 16                // u split factor
#define OSPLIT 4                 // out-GEMM split-K factor

// ---------------- scratch (no allocations allowed) ----------------
__device__ float g_qpart[KSPLIT * Bb * Dd];    // q split-K partials (8 MB)
__device__ float g_upart[USPLIT * 2 * Dd];     // u partials
__device__ float g_pacc[NSPLIT * Bb * Dd];     // unnormalized pooled partials
__device__ float g_mz[NSPLIT * Bb * 2];        // per-half (m, Z)

// ================= K1: heterogeneous prep =================
// CTA [0,512):    q split-K partials, 64x64 tile, 4x4 blocking, 2 k-iters (prefetched)
// CTA [512,576):  u partials (USPLIT=16, 32 d-rows each)
// CTA [576,1088): out bias init
__global__ void prep_kernel(const float* __restrict__ in_state,  // [B,S]
                            const float* __restrict__ Wq,        // [D,S]
                            const float* __restrict__ Wa,        // [D]
                            const float* __restrict__ Wc,        // [D,2D]
                            const float* __restrict__ bo,        // [S]
                            float* __restrict__ out,             // [B,S]
                            float* __restrict__ qpart,
                            float* __restrict__ upart) {
    const int cta = blockIdx.x;
    const int tid = threadIdx.x;  // 256 threads

    if (cta < 512) {
        __shared__ float As[16][72];
        __shared__ float Bs[16][72];
        const int z  = cta >> 4;           // 0..31
        const int g  = cta & 15;
        const int gx = g & 7;
        const int gy = g >> 3;
        const int tx = tid & 15, ty = tid >> 4;
        const int row0 = gy * 64, col0 = gx * 64;
        const int kbeg = z * (Ss / KSPLIT);   // 32 k per slice = 2 blocks of 16
        const int lm = tid >> 2;
        const int lk = (tid & 3) * 4;
        float a00=0,a01=0,a02=0,a03=0, a10=0,a11=0,a12=0,a13=0;
        float a20=0,a21=0,a22=0,a23=0, a30=0,a31=0,a32=0,a33=0;

        // prefetch both k-blocks upfront (MLP=4)
        const float* arow = &in_state[(size_t)(row0 + lm) * Ss + kbeg + lk];
        const float* brow = &Wq[(size_t)(col0 + lm) * Ss + kbeg + lk];
        float4 av0 = *(const float4*)(arow);
        float4 bv0 = *(const float4*)(brow);
        float4 av1 = *(const float4*)(arow + 16);
        float4 bv1 = *(const float4*)(brow + 16);

#pragma unroll
        for (int it = 0; it < 2; it++) {
            float4 av = it ? av1 : av0;
            float4 bv = it ? bv1 : bv0;
            if (it) __syncthreads();
            As[lk + 0][lm] = av.x; As[lk + 1][lm] = av.y;
            As[lk + 2][lm] = av.z; As[lk + 3][lm] = av.w;
            Bs[lk + 0][lm] = bv.x; Bs[lk + 1][lm] = bv.y;
            Bs[lk + 2][lm] = bv.z; Bs[lk + 3][lm] = bv.w;
            __syncthreads();
#pragma unroll
            for (int kk = 0; kk < 16; kk++) {
                float4 a4 = *(float4*)&As[kk][ty * 4];
                float4 b4 = *(float4*)&Bs[kk][tx * 4];
                a00 += a4.x*b4.x; a01 += a4.x*b4.y; a02 += a4.x*b4.z; a03 += a4.x*b4.w;
                a10 += a4.y*b4.x; a11 += a4.y*b4.y; a12 += a4.y*b4.z; a13 += a4.y*b4.w;
                a20 += a4.z*b4.x; a21 += a4.z*b4.y; a22 += a4.z*b4.z; a23 += a4.z*b4.w;
                a30 += a4.w*b4.x; a31 += a4.w*b4.y; a32 += a4.w*b4.z; a33 += a4.w*b4.w;
            }
        }
        float* base = qpart + (size_t)z * Bb * Dd + (size_t)(row0 + ty * 4) * Dd + col0 + tx * 4;
        *(float4*)(base + 0 * Dd) = make_float4(a00, a01, a02, a03);
        *(float4*)(base + 1 * Dd) = make_float4(a10, a11, a12, a13);
        *(float4*)(base + 2 * Dd) = make_float4(a20, a21, a22, a23);
        *(float4*)(base + 3 * Dd) = make_float4(a30, a31, a32, a33);
    } else if (cta < 576) {
        const int local = cta - 512;       // 0..63
        const int colchunk = local & 3;    // 256 cols each
        const int kchunk = local >> 2;     // 0..15, 32 d-rows each
        const int col = colchunk * 256 + tid;
        const int dbeg = kchunk * 32;
        float acc = 0.f;
#pragma unroll
        for (int d = dbeg; d < dbeg + 32; d++)
            acc += Wa[d] * Wc[(size_t)d * (2 * Dd) + col];
        upart[kchunk * (2 * Dd) + col] = acc;
    } else {
        const int j = (cta - 576) * 256 + tid;  // 512*256 = 131072 exactly
        out[j] = bo[j & (Ss - 1)];
    }
}

// ================= K2: flash attention, n-split halves, 2 CTAs/SM (R10-proven) ==========
__global__ __launch_bounds__(ATHREADS, 2) void attn_flash(
    const float* __restrict__ image, const float* __restrict__ qpart,
    const float* __restrict__ upart, const float* __restrict__ bq,
    float* __restrict__ pacc, float* __restrict__ mz) {
    __shared__ float spart[2][192];   // 8 warp-rows, stride 20, + pad

    const int b = blockIdx.x >> 1;
    const int c = blockIdx.x & 1;
    const int lane = threadIdx.x & 31;
    const int warp = threadIdx.x >> 5;   // 0..7
    const int d0 = warp * 64;
    const int r = lane >> 2;             // 0..7
    const int k = lane & 3;              // 0..3
    const float* imgb = image + (size_t)b * Dd * Nn + (size_t)c * COLS_PER;
    const float4* p0 = reinterpret_cast<const float4*>(imgb + (size_t)(d0 + r) * Nn) + k;

    // ---- prologue: fused logit weights ----
    const int dg0 = d0 + lane, dg1 = d0 + 32 + lane;
    float q0 = 0.f, q1 = 0.f, u10 = 0.f, u11 = 0.f, u20 = 0.f, u21 = 0.f;
#pragma unroll
    for (int p = 0; p < KSPLIT; p++) {
        q0 += qpart[((size_t)p * Bb + b) * Dd + dg0];
        q1 += qpart[((size_t)p * Bb + b) * Dd + dg1];
    }
#pragma unroll
    for (int p = 0; p < USPLIT; p++) {
        u10 += upart[p * (2 * Dd) + dg0];
        u11 += upart[p * (2 * Dd) + dg1];
        u20 += upart[p * (2 * Dd) + Dd + dg0];
        u21 += upart[p * (2 * Dd) + Dd + dg1];
    }
    const float swv0 = u10 * (q0 + bq[dg0]) + u20;
    const float swv1 = u11 * (q1 + bq[dg1]) + u21;

    float4 ra[8], rb[8], acc[8];
#pragma unroll
    for (int j = 0; j < 8; j++) acc[j] = make_float4(0.f, 0.f, 0.f, 0.f);
    float m = -INFINITY, Zl = 0.f;

#define LOADF(T, REG)                                                              \
    {                                                                              \
        _Pragma("unroll")                                                          \
        for (int j = 0; j < 8; j++) REG[j] = __ldg(&p0[(size_t)j * 1568 + (T) * 4]);\
    }
#define LOADT(REG)                                                                 \
    {                                                                              \
        _Pragma("unroll")                                                          \
        for (int j = 0; j < 8; j++)                                                \
            REG[j] = (k < 2) ? __ldg(&p0[(size_t)j * 1568 + 96])                   \
                             : make_float4(0.f, 0.f, 0.f, 0.f);                    \
    }

#define PROC(REG, PAR, TAILF)                                                      \
    {                                                                              \
        float4 s4 = make_float4(0.f, 0.f, 0.f, 0.f);                               \
        _Pragma("unroll")                                                          \
        for (int j = 0; j < 4; j++) {                                              \
            float wj = __shfl_sync(0xffffffffu, swv0, 8 * j + r);                  \
            s4.x += wj * REG[j].x; s4.y += wj * REG[j].y;                          \
            s4.z += wj * REG[j].z; s4.w += wj * REG[j].w;                          \
        }                                                                          \
        _Pragma("unroll")                                                          \
        for (int j = 4; j < 8; j++) {                                              \
            float wj = __shfl_sync(0xffffffffu, swv1, 8 * (j - 4) + r);            \
            s4.x += wj * REG[j].x; s4.y += wj * REG[j].y;                          \
            s4.z += wj * REG[j].z; s4.w += wj * REG[j].w;                          \
        }                                                                          \
        _Pragma("unroll")                                                          \
        for (int o = 4; o <= 16; o <<= 1) {                                        \
            s4.x += __shfl_xor_sync(0xffffffffu, s4.x, o);                         \
            s4.y += __shfl_xor_sync(0xffffffffu, s4.y, o);                         \
            s4.z += __shfl_xor_sync(0xffffffffu, s4.z, o);                         \
            s4.w += __shfl_xor_sync(0xffffffffu, s4.w, o);                         \
        }                                                                          \
        if (lane < 4) *(float4*)&spart[PAR][warp * 20 + lane * 4] = s4;            \
        __syncthreads();                                                           \
        float v = 0.f;                                                             \
        _Pragma("unroll")                                                          \
        for (int rr = 0; rr < 8; rr++) v += spart[PAR][rr * 20 + lane];            \
        const bool actv = (TAILF) ? (lane < 8) : (lane < 16);                      \
        float vm = actv ? v : -INFINITY;                                           \
        _Pragma("unroll")                                                          \
        for (int o = 16; o; o >>= 1)                                               \
            vm = fmaxf(vm, __shfl_xor_sync(0xffffffffu, vm, o));                   \
        float newm = fmaxf(m, vm);                                                 \
        float e = actv ? __expf(v - newm) : 0.f;                                   \
        float ts = e;                                                              \
        _Pragma("unroll")                                                          \
        for (int o = 16; o; o >>= 1) ts += __shfl_xor_sync(0xffffffffu, ts, o);    \
        const bool resc = (newm > m);                                              \
        float sc = resc ? __expf(m - newm) : 1.f;                                  \
        Zl = Zl * sc + ts;                                                         \
        m = newm;                                                                  \
        float4 e4;                                                                 \
        e4.x = __shfl_sync(0xffffffffu, e, 4 * k);                                 \
        e4.y = __shfl_sync(0xffffffffu, e, 4 * k + 1);                             \
        e4.z = __shfl_sync(0xffffffffu, e, 4 * k + 2);                             \
        e4.w = __shfl_sync(0xffffffffu, e, 4 * k + 3);                             \
        if (resc) {                                                                \
            _Pragma("unroll")                                                      \
            for (int j = 0; j < 8; j++) {                                          \
                acc[j].x = acc[j].x * sc + e4.x * REG[j].x;                        \
                acc[j].y = acc[j].y * sc + e4.y * REG[j].y;                        \
                acc[j].z = acc[j].z * sc + e4.z * REG[j].z;                        \
                acc[j].w = acc[j].w * sc + e4.w * REG[j].w;                        \
            }                                                                      \
        } else {                                                                   \
            _Pragma("unroll")                                                      \
            for (int j = 0; j < 8; j++) {                                          \
                acc[j].x += e4.x * REG[j].x;                                       \
                acc[j].y += e4.y * REG[j].y;                                       \
                acc[j].z += e4.z * REG[j].z;                                       \
                acc[j].w += e4.w * REG[j].w;                                       \
            }                                                                      \
        }                                                                          \
    }

    LOADF(0, ra)
    for (int t = 0; t < NFULL; t += 2) {
        LOADF(t + 1, rb)
        PROC(ra, 0, false)
        if (t + 2 < NFULL) { LOADF(t + 2, ra) } else { LOADT(ra) }
        PROC(rb, 1, false)
    }
    PROC(ra, 0, true)
#undef LOADF
#undef LOADT
#undef PROC

#pragma unroll
    for (int j = 0; j < 8; j++) {
        float h = acc[j].x + acc[j].y + acc[j].z + acc[j].w;
        h += __shfl_xor_sync(0xffffffffu, h, 1);
        h += __shfl_xor_sync(0xffffffffu, h, 2);
        if (k == 0) pacc[((size_t)c * Bb + b) * Dd + d0 + 8 * j + r] = h;
    }
    if (warp == 0 && lane == 0) {
        mz[(c * Bb + b) * 2 + 0] = m;
        mz[(c * Bb + b) * 2 + 1] = Zl;
    }
}

// ================= K3: out += merge(pacc) @ Wo^T, split-K x4, pipelined, fused merge ====
// Grid (16, 4, 4) = 256 CTAs x 128 threads. Tile 32x64, 4x4 blocking, K-slice 128.
__global__ __launch_bounds__(128) void gemm_out(
    const float* __restrict__ pacc,  // [2][B][D]
    const float* __restrict__ mz,    // [2][B][2]
    const float* __restrict__ Bm,    // Wo [S,D]
    float* __restrict__ C) {         // out [B,S] (bias pre-set)
    __shared__ float As[16][36];
    __shared__ float Bs[16][72];
    __shared__ float sf0[32], sf1[32];
    const int tid = threadIdx.x;       // 128
    const int gx = blockIdx.x;         // 16 col tiles (64 wide)
    const int gy = blockIdx.y;         // 4 row tiles (32 tall)
    const int z  = blockIdx.z;         // 4 k slices (128 each)
    const int tx = tid & 15, ty = tid >> 4;   // 16 x 8
    const int row0 = gy * 32, col0 = gx * 64;
    const int kbeg = z * (Dd / OSPLIT);
    const int lm = tid >> 2;           // 0..31
    const int lk = (tid & 3) * 4;      // 0,4,8,12

    // merge factors for this CTA's 32 rows
    if (tid < 32) {
        const int b = row0 + tid;
        const float m1 = mz[(0 * Bb + b) * 2 + 0], z1 = mz[(0 * Bb + b) * 2 + 1];
        const float m2 = mz[(1 * Bb + b) * 2 + 0], z2 = mz[(1 * Bb + b) * 2 + 1];
        const float M = fmaxf(m1, m2);
        const float e1 = __expf(m1 - M), e2 = __expf(m2 - M);
        const float inv = 1.f / (z1 * e1 + z2 * e2);
        sf0[tid] = e1 * inv;
        sf1[tid] = e2 * inv;
    }

    const float* pa0row = &pacc[(size_t)(0 * Bb + row0 + lm) * Dd + kbeg + lk];
    const float* pa1row = &pacc[(size_t)(1 * Bb + row0 + lm) * Dd + kbeg + lk];
    const float* wb0row = &Bm[(size_t)(col0 + lm) * Dd + kbeg + lk];
    const float* wb1row = &Bm[(size_t)(col0 + lm + 32) * Dd + kbeg + lk];

    float a00=0,a01=0,a02=0,a03=0, a10=0,a11=0,a12=0,a13=0;
    float a20=0,a21=0,a22=0,a23=0, a30=0,a31=0,a32=0,a33=0;

    // software pipeline: register double-buffer of global loads
    float4 pa0n = *(const float4*)(pa0row);
    float4 pa1n = *(const float4*)(pa1row);
    float4 b0n  = *(const float4*)(wb0row);
    float4 b1n  = *(const float4*)(wb1row);
    __syncthreads();  // sf0/sf1 ready

    const float f0 = sf0[lm], f1 = sf1[lm];

#pragma unroll
    for (int it = 0; it < 8; it++) {
        float4 pa0 = pa0n, pa1 = pa1n, b0 = b0n, b1 = b1n;
        if (it < 7) {
            const int off = (it + 1) * 16;
            pa0n = *(const float4*)(pa0row + off);
            pa1n = *(const float4*)(pa1row + off);
            b0n  = *(const float4*)(wb0row + off);
            b1n  = *(const float4*)(wb1row + off);
        }
        if (it) __syncthreads();
        As[lk + 0][lm] = f0 * pa0.x + f1 * pa1.x;
        As[lk + 1][lm] = f0 * pa0.y + f1 * pa1.y;
        As[lk + 2][lm] = f0 * pa0.z + f1 * pa1.z;
        As[lk + 3][lm] = f0 * pa0.w + f1 * pa1.w;
        Bs[lk + 0][lm] = b0.x; Bs[lk + 1][lm] = b0.y;
        Bs[lk + 2][lm] = b0.z; Bs[lk + 3][lm] = b0.w;
        Bs[lk + 0][lm + 32] = b1.x; Bs[lk + 1][lm + 32] = b1.y;
        Bs[lk + 2][lm + 32] = b1.z; Bs[lk + 3][lm + 32] = b1.w;
        __syncthreads();
#pragma unroll
        for (int kk = 0; kk < 16; kk++) {
            float4 a4 = *(float4*)&As[kk][ty * 4];
            float4 b4 = *(float4*)&Bs[kk][tx * 4];
            a00 += a4.x*b4.x; a01 += a4.x*b4.y; a02 += a4.x*b4.z; a03 += a4.x*b4.w;
            a10 += a4.y*b4.x; a11 += a4.y*b4.y; a12 += a4.y*b4.z; a13 += a4.y*b4.w;
            a20 += a4.z*b4.x; a21 += a4.z*b4.y; a22 += a4.z*b4.z; a23 += a4.z*b4.w;
            a30 += a4.w*b4.x; a31 += a4.w*b4.y; a32 += a4.w*b4.z; a33 += a4.w*b4.w;
        }
    }
    float* base = C + (size_t)(row0 + ty * 4) * Ss + col0 + tx * 4;
    atomicAdd(base + 0 * Ss + 0, a00); atomicAdd(base + 0 * Ss + 1, a01);
    atomicAdd(base + 0 * Ss + 2, a02); atomicAdd(base + 0 * Ss + 3, a03);
    atomicAdd(base + 1 * Ss + 0, a10); atomicAdd(base + 1 * Ss + 1, a11);
    atomicAdd(base + 1 * Ss + 2, a12); atomicAdd(base + 1 * Ss + 3, a13);
    atomicAdd(base + 2 * Ss + 0, a20); atomicAdd(base + 2 * Ss + 1, a21);
    atomicAdd(base + 2 * Ss + 2, a22); atomicAdd(base + 2 * Ss + 3, a23);
    atomicAdd(base + 3 * Ss + 0, a30); atomicAdd(base + 3 * Ss + 1, a31);
    atomicAdd(base + 3 * Ss + 2, a32); atomicAdd(base + 3 * Ss + 3, a33);
}

// ---------------- launcher (3 graph nodes) ----------------
extern "C" void kernel_launch(void* const* d_in, const int* in_sizes, int n_in,
                              void* d_out, int out_size) {
    const float* in_state = (const float*)d_in[0];  // [B, S]
    const float* image    = (const float*)d_in[1];  // [B, D, N]
    const float* Wq       = (const float*)d_in[2];  // [D, S]
    const float* bq       = (const float*)d_in[3];  // [D]
    const float* Wc       = (const float*)d_in[4];  // [D, 2D]
    // d_in[5] = bc (cancels in softmax)
    const float* Wa       = (const float*)d_in[6];  // [1, D]
    // d_in[7] = ba (cancels in softmax)
    const float* Wo       = (const float*)d_in[8];  // [S, D]
    const float* bo       = (const float*)d_in[9];  // [S]
    float* out = (float*)d_out;                     // [B, S]

    float* qpart_ptr;  cudaGetSymbolAddress((void**)&qpart_ptr, g_qpart);
    float* upart_ptr;  cudaGetSymbolAddress((void**)&upart_ptr, g_upart);
    float* pacc_ptr;   cudaGetSymbolAddress((void**)&pacc_ptr, g_pacc);
    float* mz_ptr;     cudaGetSymbolAddress((void**)&mz_ptr, g_mz);

    // K1: q-partials (splitk32, prefetched) + u-partials + out-bias
    prep_kernel<<<1088, 256>>>(in_state, Wq, Wa, Wc, bo, out, qpart_ptr, upart_ptr);

    // K2: flash attention over column halves (256 co-resident CTAs)
    attn_flash<<<Bb * NSPLIT, ATHREADS>>>(image, qpart_ptr, upart_ptr, bq, pacc_ptr, mz_ptr);

    // K3: out += merge(pacc) @ Wo^T (split-K x4, pipelined, fused combine)
    {
        dim3 grid(16, 4, 4);
        gemm_out<<<grid, 128>>>(pacc_ptr, mz_ptr, Wo, out);
    }
}

// round 13
// speedup vs baseline: 1.0992x; 1.0702x over previous
#include <cuda_runtime.h>
#include <math.h>
#include <stdint.h>

#define Bb 128
#define Ss 1024
#define Dd 512
#define Nn 784

#define NSPLIT 2
#define COLS_PER (Nn / NSPLIT)   // 392
#define NFULL 24                 // full 16-col tiles per half (384 cols) + 8-col tail
#define ATHREADS 256             // 8 warps; warp w owns d-rows [64w, 64w+64)
#define KSPLIT 16                // q-GEMM split-K factor
#define USPLIT 16                // u split factor
#define OSPLIT 8                 // out-GEMM split-K factor

// ---------------- scratch (no allocations allowed) ----------------
__device__ float g_qpart[KSPLIT * Bb * Dd];    // q split-K partials (4 MB)
__device__ float g_upart[USPLIT * 2 * Dd];     // u partials
__device__ float g_pacc[NSPLIT * Bb * Dd];     // unnormalized pooled partials
__device__ float g_mz[NSPLIT * Bb * 2];        // per-half (m, Z)

// ================= K1: heterogeneous prep =================
// CTA [0,256):   q split-K partials, 64x64 tile, 4x4 blocking, 4 k-blocks ALL prefetched
// CTA [256,320): u partials (USPLIT=16, 32 d-rows each)
// CTA [320,448): out bias init (float4)
__global__ void prep_kernel(const float* __restrict__ in_state,  // [B,S]
                            const float* __restrict__ Wq,        // [D,S]
                            const float* __restrict__ Wa,        // [D]
                            const float* __restrict__ Wc,        // [D,2D]
                            const float* __restrict__ bo,        // [S]
                            float* __restrict__ out,             // [B,S]
                            float* __restrict__ qpart,
                            float* __restrict__ upart) {
    const int cta = blockIdx.x;
    const int tid = threadIdx.x;  // 256 threads

    if (cta < 256) {
        __shared__ float As[16][72];
        __shared__ float Bs[16][72];
        const int z  = cta >> 4;           // 0..15
        const int g  = cta & 15;
        const int gx = g & 7;
        const int gy = g >> 3;
        const int tx = tid & 15, ty = tid >> 4;
        const int row0 = gy * 64, col0 = gx * 64;
        const int kbeg = z * (Ss / KSPLIT);   // 64 k per slice = 4 blocks of 16
        const int lm = tid >> 2;
        const int lk = (tid & 3) * 4;
        float a00=0,a01=0,a02=0,a03=0, a10=0,a11=0,a12=0,a13=0;
        float a20=0,a21=0,a22=0,a23=0, a30=0,a31=0,a32=0,a33=0;

        // prefetch ALL 4 k-blocks upfront (MLP=8): one exposed DRAM latency
        const float* arow = &in_state[(size_t)(row0 + lm) * Ss + kbeg + lk];
        const float* brow = &Wq[(size_t)(col0 + lm) * Ss + kbeg + lk];
        float4 av[4], bv[4];
#pragma unroll
        for (int i = 0; i < 4; i++) {
            av[i] = *(const float4*)(arow + i * 16);
            bv[i] = *(const float4*)(brow + i * 16);
        }

#pragma unroll
        for (int it = 0; it < 4; it++) {
            if (it) __syncthreads();
            As[lk + 0][lm] = av[it].x; As[lk + 1][lm] = av[it].y;
            As[lk + 2][lm] = av[it].z; As[lk + 3][lm] = av[it].w;
            Bs[lk + 0][lm] = bv[it].x; Bs[lk + 1][lm] = bv[it].y;
            Bs[lk + 2][lm] = bv[it].z; Bs[lk + 3][lm] = bv[it].w;
            __syncthreads();
#pragma unroll
            for (int kk = 0; kk < 16; kk++) {
                float4 a4 = *(float4*)&As[kk][ty * 4];
                float4 b4 = *(float4*)&Bs[kk][tx * 4];
                a00 += a4.x*b4.x; a01 += a4.x*b4.y; a02 += a4.x*b4.z; a03 += a4.x*b4.w;
                a10 += a4.y*b4.x; a11 += a4.y*b4.y; a12 += a4.y*b4.z; a13 += a4.y*b4.w;
                a20 += a4.z*b4.x; a21 += a4.z*b4.y; a22 += a4.z*b4.z; a23 += a4.z*b4.w;
                a30 += a4.w*b4.x; a31 += a4.w*b4.y; a32 += a4.w*b4.z; a33 += a4.w*b4.w;
            }
        }
        float* base = qpart + (size_t)z * Bb * Dd + (size_t)(row0 + ty * 4) * Dd + col0 + tx * 4;
        *(float4*)(base + 0 * Dd) = make_float4(a00, a01, a02, a03);
        *(float4*)(base + 1 * Dd) = make_float4(a10, a11, a12, a13);
        *(float4*)(base + 2 * Dd) = make_float4(a20, a21, a22, a23);
        *(float4*)(base + 3 * Dd) = make_float4(a30, a31, a32, a33);
    } else if (cta < 320) {
        const int local = cta - 256;       // 0..63
        const int colchunk = local & 3;    // 256 cols each
        const int kchunk = local >> 2;     // 0..15, 32 d-rows each
        const int col = colchunk * 256 + tid;
        const int dbeg = kchunk * 32;
        float acc = 0.f;
#pragma unroll
        for (int d = dbeg; d < dbeg + 32; d++)
            acc += Wa[d] * Wc[(size_t)d * (2 * Dd) + col];
        upart[kchunk * (2 * Dd) + col] = acc;
    } else {
        // bias init, float4: 128 CTAs x 256 thr x 1 float4 = 32768 float4 = 131072 floats
        const int j4 = (cta - 320) * 256 + tid;
        const float4 bv = *(const float4*)&bo[(j4 * 4) & (Ss - 1)];
        *(float4*)&out[j4 * 4] = bv;
    }
}

// ================= K2: flash attention, n-split halves, 2 CTAs/SM (R10-proven) ==========
__global__ __launch_bounds__(ATHREADS, 2) void attn_flash(
    const float* __restrict__ image, const float* __restrict__ qpart,
    const float* __restrict__ upart, const float* __restrict__ bq,
    float* __restrict__ pacc, float* __restrict__ mz) {
    __shared__ float spart[2][192];   // 8 warp-rows, stride 20, + pad

    const int b = blockIdx.x >> 1;
    const int c = blockIdx.x & 1;
    const int lane = threadIdx.x & 31;
    const int warp = threadIdx.x >> 5;   // 0..7
    const int d0 = warp * 64;
    const int r = lane >> 2;             // 0..7
    const int k = lane & 3;              // 0..3
    const float* imgb = image + (size_t)b * Dd * Nn + (size_t)c * COLS_PER;
    const float4* p0 = reinterpret_cast<const float4*>(imgb + (size_t)(d0 + r) * Nn) + k;

    // ---- prologue: fused logit weights ----
    const int dg0 = d0 + lane, dg1 = d0 + 32 + lane;
    float q0 = 0.f, q1 = 0.f, u10 = 0.f, u11 = 0.f, u20 = 0.f, u21 = 0.f;
#pragma unroll
    for (int p = 0; p < KSPLIT; p++) {
        q0 += qpart[((size_t)p * Bb + b) * Dd + dg0];
        q1 += qpart[((size_t)p * Bb + b) * Dd + dg1];
    }
#pragma unroll
    for (int p = 0; p < USPLIT; p++) {
        u10 += upart[p * (2 * Dd) + dg0];
        u11 += upart[p * (2 * Dd) + dg1];
        u20 += upart[p * (2 * Dd) + Dd + dg0];
        u21 += upart[p * (2 * Dd) + Dd + dg1];
    }
    const float swv0 = u10 * (q0 + bq[dg0]) + u20;
    const float swv1 = u11 * (q1 + bq[dg1]) + u21;

    float4 ra[8], rb[8], acc[8];
#pragma unroll
    for (int j = 0; j < 8; j++) acc[j] = make_float4(0.f, 0.f, 0.f, 0.f);
    float m = -INFINITY, Zl = 0.f;

#define LOADF(T, REG)                                                              \
    {                                                                              \
        _Pragma("unroll")                                                          \
        for (int j = 0; j < 8; j++) REG[j] = __ldg(&p0[(size_t)j * 1568 + (T) * 4]);\
    }
#define LOADT(REG)                                                                 \
    {                                                                              \
        _Pragma("unroll")                                                          \
        for (int j = 0; j < 8; j++)                                                \
            REG[j] = (k < 2) ? __ldg(&p0[(size_t)j * 1568 + 96])                   \
                             : make_float4(0.f, 0.f, 0.f, 0.f);                    \
    }

#define PROC(REG, PAR, TAILF)                                                      \
    {                                                                              \
        float4 s4 = make_float4(0.f, 0.f, 0.f, 0.f);                               \
        _Pragma("unroll")                                                          \
        for (int j = 0; j < 4; j++) {                                              \
            float wj = __shfl_sync(0xffffffffu, swv0, 8 * j + r);                  \
            s4.x += wj * REG[j].x; s4.y += wj * REG[j].y;                          \
            s4.z += wj * REG[j].z; s4.w += wj * REG[j].w;                          \
        }                                                                          \
        _Pragma("unroll")                                                          \
        for (int j = 4; j < 8; j++) {                                              \
            float wj = __shfl_sync(0xffffffffu, swv1, 8 * (j - 4) + r);            \
            s4.x += wj * REG[j].x; s4.y += wj * REG[j].y;                          \
            s4.z += wj * REG[j].z; s4.w += wj * REG[j].w;                          \
        }                                                                          \
        _Pragma("unroll")                                                          \
        for (int o = 4; o <= 16; o <<= 1) {                                        \
            s4.x += __shfl_xor_sync(0xffffffffu, s4.x, o);                         \
            s4.y += __shfl_xor_sync(0xffffffffu, s4.y, o);                         \
            s4.z += __shfl_xor_sync(0xffffffffu, s4.z, o);                         \
            s4.w += __shfl_xor_sync(0xffffffffu, s4.w, o);                         \
        }                                                                          \
        if (lane < 4) *(float4*)&spart[PAR][warp * 20 + lane * 4] = s4;            \
        __syncthreads();                                                           \
        float v = 0.f;                                                             \
        _Pragma("unroll")                                                          \
        for (int rr = 0; rr < 8; rr++) v += spart[PAR][rr * 20 + lane];            \
        const bool actv = (TAILF) ? (lane < 8) : (lane < 16);                      \
        float vm = actv ? v : -INFINITY;                                           \
        _Pragma("unroll")                                                          \
        for (int o = 16; o; o >>= 1)                                               \
            vm = fmaxf(vm, __shfl_xor_sync(0xffffffffu, vm, o));                   \
        float newm = fmaxf(m, vm);                                                 \
        float e = actv ? __expf(v - newm) : 0.f;                                   \
        float ts = e;                                                              \
        _Pragma("unroll")                                                          \
        for (int o = 16; o; o >>= 1) ts += __shfl_xor_sync(0xffffffffu, ts, o);    \
        const bool resc = (newm > m);                                              \
        float sc = resc ? __expf(m - newm) : 1.f;                                  \
        Zl = Zl * sc + ts;                                                         \
        m = newm;                                                                  \
        float4 e4;                                                                 \
        e4.x = __shfl_sync(0xffffffffu, e, 4 * k);                                 \
        e4.y = __shfl_sync(0xffffffffu, e, 4 * k + 1);                             \
        e4.z = __shfl_sync(0xffffffffu, e, 4 * k + 2);                             \
        e4.w = __shfl_sync(0xffffffffu, e, 4 * k + 3);                             \
        if (resc) {                                                                \
            _Pragma("unroll")                                                      \
            for (int j = 0; j < 8; j++) {                                          \
                acc[j].x = acc[j].x * sc + e4.x * REG[j].x;                        \
                acc[j].y = acc[j].y * sc + e4.y * REG[j].y;                        \
                acc[j].z = acc[j].z * sc + e4.z * REG[j].z;                        \
                acc[j].w = acc[j].w * sc + e4.w * REG[j].w;                        \
            }                                                                      \
        } else {                                                                   \
            _Pragma("unroll")                                                      \
            for (int j = 0; j < 8; j++) {                                          \
                acc[j].x += e4.x * REG[j].x;                                       \
                acc[j].y += e4.y * REG[j].y;                                       \
                acc[j].z += e4.z * REG[j].z;                                       \
                acc[j].w += e4.w * REG[j].w;                                       \
            }                                                                      \
        }                                                                          \
    }

    LOADF(0, ra)
    for (int t = 0; t < NFULL; t += 2) {
        LOADF(t + 1, rb)
        PROC(ra, 0, false)
        if (t + 2 < NFULL) { LOADF(t + 2, ra) } else { LOADT(ra) }
        PROC(rb, 1, false)
    }
    PROC(ra, 0, true)
#undef LOADF
#undef LOADT
#undef PROC

#pragma unroll
    for (int j = 0; j < 8; j++) {
        float h = acc[j].x + acc[j].y + acc[j].z + acc[j].w;
        h += __shfl_xor_sync(0xffffffffu, h, 1);
        h += __shfl_xor_sync(0xffffffffu, h, 2);
        if (k == 0) pacc[((size_t)c * Bb + b) * Dd + d0 + 8 * j + r] = h;
    }
    if (warp == 0 && lane == 0) {
        mz[(c * Bb + b) * 2 + 0] = m;
        mz[(c * Bb + b) * 2 + 1] = Zl;
    }
}

// ================= K3: out += merge(pacc) @ Wo^T, 64x64 tile, split-K x8, pipelined =====
// Grid (16, 2, 8) = 256 CTAs x 256 threads; fused softmax merge in A-load.
__global__ void gemm_out(const float* __restrict__ pacc,  // [2][B][D]
                         const float* __restrict__ mz,    // [2][B][2]
                         const float* __restrict__ Bm,    // Wo [S,D]
                         float* __restrict__ C) {         // out [B,S] (bias pre-set)
    __shared__ float As[16][72];
    __shared__ float Bs[16][72];
    __shared__ float sf0[64], sf1[64];
    const int tid = threadIdx.x;       // 256
    const int gx = blockIdx.x;         // 16 col tiles (64 wide)
    const int gy = blockIdx.y;         // 2 row tiles (64 tall)
    const int z  = blockIdx.z;         // 8 k slices (64 each = 4 blocks)
    const int tx = tid & 15, ty = tid >> 4;
    const int row0 = gy * 64, col0 = gx * 64;
    const int kbeg = z * (Dd / OSPLIT);
    const int lm = tid >> 2;           // 0..63
    const int lk = (tid & 3) * 4;

    // merge factors for this CTA's 64 rows
    if (tid < 64) {
        const int b = row0 + tid;
        const float m1 = mz[(0 * Bb + b) * 2 + 0], z1 = mz[(0 * Bb + b) * 2 + 1];
        const float m2 = mz[(1 * Bb + b) * 2 + 0], z2 = mz[(1 * Bb + b) * 2 + 1];
        const float M = fmaxf(m1, m2);
        const float e1 = __expf(m1 - M), e2 = __expf(m2 - M);
        const float inv = 1.f / (z1 * e1 + z2 * e2);
        sf0[tid] = e1 * inv;
        sf1[tid] = e2 * inv;
    }

    const float* pa0row = &pacc[(size_t)(0 * Bb + row0 + lm) * Dd + kbeg + lk];
    const float* pa1row = &pacc[(size_t)(1 * Bb + row0 + lm) * Dd + kbeg + lk];
    const float* wbrow  = &Bm[(size_t)(col0 + lm) * Dd + kbeg + lk];

    float a00=0,a01=0,a02=0,a03=0, a10=0,a11=0,a12=0,a13=0;
    float a20=0,a21=0,a22=0,a23=0, a30=0,a31=0,a32=0,a33=0;

    // register-pipelined loads (3 float4 per k-block)
    float4 pa0n = *(const float4*)(pa0row);
    float4 pa1n = *(const float4*)(pa1row);
    float4 bvn  = *(const float4*)(wbrow);
    __syncthreads();  // sf0/sf1 ready
    const float f0 = sf0[lm], f1 = sf1[lm];

#pragma unroll
    for (int it = 0; it < 4; it++) {
        float4 pa0 = pa0n, pa1 = pa1n, bv = bvn;
        if (it < 3) {
            const int off = (it + 1) * 16;
            pa0n = *(const float4*)(pa0row + off);
            pa1n = *(const float4*)(pa1row + off);
            bvn  = *(const float4*)(wbrow + off);
        }
        if (it) __syncthreads();
        As[lk + 0][lm] = f0 * pa0.x + f1 * pa1.x;
        As[lk + 1][lm] = f0 * pa0.y + f1 * pa1.y;
        As[lk + 2][lm] = f0 * pa0.z + f1 * pa1.z;
        As[lk + 3][lm] = f0 * pa0.w + f1 * pa1.w;
        Bs[lk + 0][lm] = bv.x; Bs[lk + 1][lm] = bv.y;
        Bs[lk + 2][lm] = bv.z; Bs[lk + 3][lm] = bv.w;
        __syncthreads();
#pragma unroll
        for (int kk = 0; kk < 16; kk++) {
            float4 a4 = *(float4*)&As[kk][ty * 4];
            float4 b4 = *(float4*)&Bs[kk][tx * 4];
            a00 += a4.x*b4.x; a01 += a4.x*b4.y; a02 += a4.x*b4.z; a03 += a4.x*b4.w;
            a10 += a4.y*b4.x; a11 += a4.y*b4.y; a12 += a4.y*b4.z; a13 += a4.y*b4.w;
            a20 += a4.z*b4.x; a21 += a4.z*b4.y; a22 += a4.z*b4.z; a23 += a4.z*b4.w;
            a30 += a4.w*b4.x; a31 += a4.w*b4.y; a32 += a4.w*b4.z; a33 += a4.w*b4.w;
        }
    }
    float* base = C + (size_t)(row0 + ty * 4) * Ss + col0 + tx * 4;
    atomicAdd(base + 0 * Ss + 0, a00); atomicAdd(base + 0 * Ss + 1, a01);
    atomicAdd(base + 0 * Ss + 2, a02); atomicAdd(base + 0 * Ss + 3, a03);
    atomicAdd(base + 1 * Ss + 0, a10); atomicAdd(base + 1 * Ss + 1, a11);
    atomicAdd(base + 1 * Ss + 2, a12); atomicAdd(base + 1 * Ss + 3, a13);
    atomicAdd(base + 2 * Ss + 0, a20); atomicAdd(base + 2 * Ss + 1, a21);
    atomicAdd(base + 2 * Ss + 2, a22); atomicAdd(base + 2 * Ss + 3, a23);
    atomicAdd(base + 3 * Ss + 0, a30); atomicAdd(base + 3 * Ss + 1, a31);
    atomicAdd(base + 3 * Ss + 2, a32); atomicAdd(base + 3 * Ss + 3, a33);
}

// ---------------- launcher (3 graph nodes) ----------------
extern "C" void kernel_launch(void* const* d_in, const int* in_sizes, int n_in,
                              void* d_out, int out_size) {
    const float* in_state = (const float*)d_in[0];  // [B, S]
    const float* image    = (const float*)d_in[1];  // [B, D, N]
    const float* Wq       = (const float*)d_in[2];  // [D, S]
    const float* bq       = (const float*)d_in[3];  // [D]
    const float* Wc       = (const float*)d_in[4];  // [D, 2D]
    // d_in[5] = bc (cancels in softmax)
    const float* Wa       = (const float*)d_in[6];  // [1, D]
    // d_in[7] = ba (cancels in softmax)
    const float* Wo       = (const float*)d_in[8];  // [S, D]
    const float* bo       = (const float*)d_in[9];  // [S]
    float* out = (float*)d_out;                     // [B, S]

    float* qpart_ptr;  cudaGetSymbolAddress((void**)&qpart_ptr, g_qpart);
    float* upart_ptr;  cudaGetSymbolAddress((void**)&upart_ptr, g_upart);
    float* pacc_ptr;   cudaGetSymbolAddress((void**)&pacc_ptr, g_pacc);
    float* mz_ptr;     cudaGetSymbolAddress((void**)&mz_ptr, g_mz);

    // K1: q-partials (splitk16, full prefetch) + u-partials + out-bias (float4)
    prep_kernel<<<448, 256>>>(in_state, Wq, Wa, Wc, bo, out, qpart_ptr, upart_ptr);

    // K2: flash attention over column halves (256 co-resident CTAs)
    attn_flash<<<Bb * NSPLIT, ATHREADS>>>(image, qpart_ptr, upart_ptr, bq, pacc_ptr, mz_ptr);

    // K3: out += merge(pacc) @ Wo^T (split-K x8, 8-warp CTAs, pipelined, fused merge)
    {
        dim3 grid(16, 2, 8);
        gemm_out<<<grid, 256>>>(pacc_ptr, mz_ptr, Wo, out);
    }
}

// round 14
// speedup vs baseline: 1.1003x; 1.0010x over previous
#include <cuda_runtime.h>
#include <math.h>
#include <stdint.h>

#define Bb 128
#define Ss 1024
#define Dd 512
#define Nn 784

#define NSPLIT 2
#define COLS_PER (Nn / NSPLIT)   // 392
#define NFULL 24                 // full 16-col tiles per half + 8-col tail
#define GRIDSZ 256
#define THREADS 256
#define KSPLIT 16                // q-GEMM split-K factor
#define USPLIT 16                // u split factor
#define OSPLIT 8                 // out-GEMM split-K factor

// ---------------- scratch (no allocations allowed) ----------------
__device__ float g_qpart[KSPLIT * Bb * Dd];    // q split-K partials (4 MB)
__device__ float g_upart[USPLIT * 2 * Dd];     // u partials
__device__ float g_pacc[NSPLIT * Bb * Dd];     // unnormalized pooled partials
__device__ float g_mz[NSPLIT * Bb * 2];        // per-half (m, Z)
__device__ unsigned long long g_bar = 0ULL;    // monotonic grid barrier (never reset)

// ---------------- grid barrier: monotonic counter, replay-safe ----------------
__device__ __forceinline__ void grid_sync() {
    __syncthreads();
    if (threadIdx.x == 0) {
        __threadfence();  // release: all our global writes visible before arrival
        unsigned long long arrival = atomicAdd(&g_bar, 1ULL);
        unsigned long long goal = (arrival / GRIDSZ + 1ULL) * GRIDSZ;
        while (atomicAdd(&g_bar, 0ULL) < goal) __nanosleep(64);
    }
    __syncthreads();
}

// ================= single fused kernel: prep -> attn -> out-GEMM =================
__global__ __launch_bounds__(THREADS, 2) void fused_kernel(
    const float* __restrict__ in_state,  // [B,S]
    const float* __restrict__ image,     // [B,D,N]
    const float* __restrict__ Wq,        // [D,S]
    const float* __restrict__ bq,        // [D]
    const float* __restrict__ Wa,        // [D]
    const float* __restrict__ Wc,        // [D,2D]
    const float* __restrict__ Wo,        // [S,D]
    const float* __restrict__ bo,        // [S]
    float* __restrict__ out) {           // [B,S]
    __shared__ float As[16][72];
    __shared__ float Bs[16][72];
    __shared__ float spart[2][192];
    __shared__ float sf0[64], sf1[64];

    const int cta = blockIdx.x;   // 0..255
    const int tid = threadIdx.x;  // 0..255
    const int lane = tid & 31;
    const int warp = tid >> 5;

    // ======================= PHASE 0: prep =======================
    {
        // ---- q split-K tile (all 256 CTAs) ----
        const int z  = cta >> 4;           // 0..15
        const int g  = cta & 15;
        const int gx = g & 7;
        const int gy = g >> 3;
        const int tx = tid & 15, ty = tid >> 4;
        const int row0 = gy * 64, col0 = gx * 64;
        const int kbeg = z * (Ss / KSPLIT);   // 64 k per slice
        const int lm = tid >> 2;
        const int lk = (tid & 3) * 4;
        float a00=0,a01=0,a02=0,a03=0, a10=0,a11=0,a12=0,a13=0;
        float a20=0,a21=0,a22=0,a23=0, a30=0,a31=0,a32=0,a33=0;

        const float* arow = &in_state[(size_t)(row0 + lm) * Ss + kbeg + lk];
        const float* brow = &Wq[(size_t)(col0 + lm) * Ss + kbeg + lk];
        float4 av[4], bv[4];
#pragma unroll
        for (int i = 0; i < 4; i++) {
            av[i] = *(const float4*)(arow + i * 16);
            bv[i] = *(const float4*)(brow + i * 16);
        }
#pragma unroll
        for (int it = 0; it < 4; it++) {
            if (it) __syncthreads();
            As[lk + 0][lm] = av[it].x; As[lk + 1][lm] = av[it].y;
            As[lk + 2][lm] = av[it].z; As[lk + 3][lm] = av[it].w;
            Bs[lk + 0][lm] = bv[it].x; Bs[lk + 1][lm] = bv[it].y;
            Bs[lk + 2][lm] = bv[it].z; Bs[lk + 3][lm] = bv[it].w;
            __syncthreads();
#pragma unroll
            for (int kk = 0; kk < 16; kk++) {
                float4 a4 = *(float4*)&As[kk][ty * 4];
                float4 b4 = *(float4*)&Bs[kk][tx * 4];
                a00 += a4.x*b4.x; a01 += a4.x*b4.y; a02 += a4.x*b4.z; a03 += a4.x*b4.w;
                a10 += a4.y*b4.x; a11 += a4.y*b4.y; a12 += a4.y*b4.z; a13 += a4.y*b4.w;
                a20 += a4.z*b4.x; a21 += a4.z*b4.y; a22 += a4.z*b4.z; a23 += a4.z*b4.w;
                a30 += a4.w*b4.x; a31 += a4.w*b4.y; a32 += a4.w*b4.z; a33 += a4.w*b4.w;
            }
        }
        float* base = g_qpart + (size_t)z * Bb * Dd + (size_t)(row0 + ty * 4) * Dd + col0 + tx * 4;
        *(float4*)(base + 0 * Dd) = make_float4(a00, a01, a02, a03);
        *(float4*)(base + 1 * Dd) = make_float4(a10, a11, a12, a13);
        *(float4*)(base + 2 * Dd) = make_float4(a20, a21, a22, a23);
        *(float4*)(base + 3 * Dd) = make_float4(a30, a31, a32, a33);

        // ---- extra light work on low CTAs ----
        if (cta < 64) {
            // u partials: colchunk = cta&3 (256 cols), kchunk = cta>>2 (32 d-rows)
            const int col = (cta & 3) * 256 + tid;
            const int dbeg = (cta >> 2) * 32;
            float acc = 0.f;
#pragma unroll
            for (int d = dbeg; d < dbeg + 32; d++)
                acc += Wa[d] * Wc[(size_t)d * (2 * Dd) + col];
            g_upart[(cta >> 2) * (2 * Dd) + col] = acc;
        } else if (cta < 192) {
            // bias init (float4): 128 CTAs x 256 thr x 1 float4 = 131072 floats
            const int j4 = (cta - 64) * 256 + tid;
            const float4 bvv = *(const float4*)&bo[(j4 * 4) & (Ss - 1)];
            *(float4*)&out[j4 * 4] = bvv;
        }
    }

    grid_sync();

    // ======================= PHASE 1: flash attention =======================
    {
        const int b = cta >> 1;
        const int c = cta & 1;
        const int d0 = warp * 64;
        const int r = lane >> 2;             // 0..7
        const int k = lane & 3;              // 0..3
        const float* imgb = image + (size_t)b * Dd * Nn + (size_t)c * COLS_PER;
        const float4* p0 = reinterpret_cast<const float4*>(imgb + (size_t)(d0 + r) * Nn) + k;

        // prologue: fused logit weights
        const int dg0 = d0 + lane, dg1 = d0 + 32 + lane;
        float q0 = 0.f, q1 = 0.f, u10 = 0.f, u11 = 0.f, u20 = 0.f, u21 = 0.f;
#pragma unroll
        for (int p = 0; p < KSPLIT; p++) {
            q0 += g_qpart[((size_t)p * Bb + b) * Dd + dg0];
            q1 += g_qpart[((size_t)p * Bb + b) * Dd + dg1];
        }
#pragma unroll
        for (int p = 0; p < USPLIT; p++) {
            u10 += g_upart[p * (2 * Dd) + dg0];
            u11 += g_upart[p * (2 * Dd) + dg1];
            u20 += g_upart[p * (2 * Dd) + Dd + dg0];
            u21 += g_upart[p * (2 * Dd) + Dd + dg1];
        }
        const float swv0 = u10 * (q0 + bq[dg0]) + u20;
        const float swv1 = u11 * (q1 + bq[dg1]) + u21;

        float4 ra[8], rb[8], acc[8];
#pragma unroll
        for (int j = 0; j < 8; j++) acc[j] = make_float4(0.f, 0.f, 0.f, 0.f);
        float m = -INFINITY, Zl = 0.f;

#define LOADF(T, REG)                                                              \
    {                                                                              \
        _Pragma("unroll")                                                          \
        for (int j = 0; j < 8; j++) REG[j] = __ldg(&p0[(size_t)j * 1568 + (T) * 4]);\
    }
#define LOADT(REG)                                                                 \
    {                                                                              \
        _Pragma("unroll")                                                          \
        for (int j = 0; j < 8; j++)                                                \
            REG[j] = (k < 2) ? __ldg(&p0[(size_t)j * 1568 + 96])                   \
                             : make_float4(0.f, 0.f, 0.f, 0.f);                    \
    }
#define PROC(REG, PAR, TAILF)                                                      \
    {                                                                              \
        float4 s4 = make_float4(0.f, 0.f, 0.f, 0.f);                               \
        _Pragma("unroll")                                                          \
        for (int j = 0; j < 4; j++) {                                              \
            float wj = __shfl_sync(0xffffffffu, swv0, 8 * j + r);                  \
            s4.x += wj * REG[j].x; s4.y += wj * REG[j].y;                          \
            s4.z += wj * REG[j].z; s4.w += wj * REG[j].w;                          \
        }                                                                          \
        _Pragma("unroll")                                                          \
        for (int j = 4; j < 8; j++) {                                              \
            float wj = __shfl_sync(0xffffffffu, swv1, 8 * (j - 4) + r);            \
            s4.x += wj * REG[j].x; s4.y += wj * REG[j].y;                          \
            s4.z += wj * REG[j].z; s4.w += wj * REG[j].w;                          \
        }                                                                          \
        _Pragma("unroll")                                                          \
        for (int o = 4; o <= 16; o <<= 1) {                                        \
            s4.x += __shfl_xor_sync(0xffffffffu, s4.x, o);                         \
            s4.y += __shfl_xor_sync(0xffffffffu, s4.y, o);                         \
            s4.z += __shfl_xor_sync(0xffffffffu, s4.z, o);                         \
            s4.w += __shfl_xor_sync(0xffffffffu, s4.w, o);                         \
        }                                                                          \
        if (lane < 4) *(float4*)&spart[PAR][warp * 20 + lane * 4] = s4;            \
        __syncthreads();                                                           \
        float v = 0.f;                                                             \
        _Pragma("unroll")                                                          \
        for (int rr = 0; rr < 8; rr++) v += spart[PAR][rr * 20 + lane];            \
        const bool actv = (TAILF) ? (lane < 8) : (lane < 16);                      \
        float vm = actv ? v : -INFINITY;                                           \
        _Pragma("unroll")                                                          \
        for (int o = 16; o; o >>= 1)                                               \
            vm = fmaxf(vm, __shfl_xor_sync(0xffffffffu, vm, o));                   \
        float newm = fmaxf(m, vm);                                                 \
        float e = actv ? __expf(v - newm) : 0.f;                                   \
        float ts = e;                                                              \
        _Pragma("unroll")                                                          \
        for (int o = 16; o; o >>= 1) ts += __shfl_xor_sync(0xffffffffu, ts, o);    \
        const bool resc = (newm > m);                                              \
        float sc = resc ? __expf(m - newm) : 1.f;                                  \
        Zl = Zl * sc + ts;                                                         \
        m = newm;                                                                  \
        float4 e4;                                                                 \
        e4.x = __shfl_sync(0xffffffffu, e, 4 * k);                                 \
        e4.y = __shfl_sync(0xffffffffu, e, 4 * k + 1);                             \
        e4.z = __shfl_sync(0xffffffffu, e, 4 * k + 2);                             \
        e4.w = __shfl_sync(0xffffffffu, e, 4 * k + 3);                             \
        if (resc) {                                                                \
            _Pragma("unroll")                                                      \
            for (int j = 0; j < 8; j++) {                                          \
                acc[j].x = acc[j].x * sc + e4.x * REG[j].x;                        \
                acc[j].y = acc[j].y * sc + e4.y * REG[j].y;                        \
                acc[j].z = acc[j].z * sc + e4.z * REG[j].z;                        \
                acc[j].w = acc[j].w * sc + e4.w * REG[j].w;                        \
            }                                                                      \
        } else {                                                                   \
            _Pragma("unroll")                                                      \
            for (int j = 0; j < 8; j++) {                                          \
                acc[j].x += e4.x * REG[j].x;                                       \
                acc[j].y += e4.y * REG[j].y;                                       \
                acc[j].z += e4.z * REG[j].z;                                       \
                acc[j].w += e4.w * REG[j].w;                                       \
            }                                                                      \
        }                                                                          \
    }

        LOADF(0, ra)
        for (int t = 0; t < NFULL; t += 2) {
            LOADF(t + 1, rb)
            PROC(ra, 0, false)
            if (t + 2 < NFULL) { LOADF(t + 2, ra) } else { LOADT(ra) }
            PROC(rb, 1, false)
        }
        PROC(ra, 0, true)
#undef LOADF
#undef LOADT
#undef PROC

#pragma unroll
        for (int j = 0; j < 8; j++) {
            float h = acc[j].x + acc[j].y + acc[j].z + acc[j].w;
            h += __shfl_xor_sync(0xffffffffu, h, 1);
            h += __shfl_xor_sync(0xffffffffu, h, 2);
            if (k == 0) g_pacc[((size_t)c * Bb + b) * Dd + d0 + 8 * j + r] = h;
        }
        if (warp == 0 && lane == 0) {
            g_mz[(c * Bb + b) * 2 + 0] = m;
            g_mz[(c * Bb + b) * 2 + 1] = Zl;
        }
    }

    grid_sync();

    // ======================= PHASE 2: out += merge(pacc) @ Wo^T =======================
    {
        const int gx = cta & 15;           // 16 col tiles (64 wide)
        const int gy = (cta >> 4) & 1;     // 2 row tiles (64 tall)
        const int z  = cta >> 5;           // 8 k slices (64 each)
        const int tx = tid & 15, ty = tid >> 4;
        const int row0 = gy * 64, col0 = gx * 64;
        const int kbeg = z * (Dd / OSPLIT);
        const int lm = tid >> 2;
        const int lk = (tid & 3) * 4;

        if (tid < 64) {
            const int b = row0 + tid;
            const float m1 = g_mz[(0 * Bb + b) * 2 + 0], z1 = g_mz[(0 * Bb + b) * 2 + 1];
            const float m2 = g_mz[(1 * Bb + b) * 2 + 0], z2 = g_mz[(1 * Bb + b) * 2 + 1];
            const float M = fmaxf(m1, m2);
            const float e1 = __expf(m1 - M), e2 = __expf(m2 - M);
            const float inv = 1.f / (z1 * e1 + z2 * e2);
            sf0[tid] = e1 * inv;
            sf1[tid] = e2 * inv;
        }

        const float* pa0row = &g_pacc[(size_t)(0 * Bb + row0 + lm) * Dd + kbeg + lk];
        const float* pa1row = &g_pacc[(size_t)(1 * Bb + row0 + lm) * Dd + kbeg + lk];
        const float* wbrow  = &Wo[(size_t)(col0 + lm) * Dd + kbeg + lk];

        float a00=0,a01=0,a02=0,a03=0, a10=0,a11=0,a12=0,a13=0;
        float a20=0,a21=0,a22=0,a23=0, a30=0,a31=0,a32=0,a33=0;

        float4 pa0n = *(const float4*)(pa0row);
        float4 pa1n = *(const float4*)(pa1row);
        float4 bvn  = *(const float4*)(wbrow);
        __syncthreads();  // sf0/sf1 ready
        const float f0 = sf0[lm], f1 = sf1[lm];

#pragma unroll
        for (int it = 0; it < 4; it++) {
            float4 pa0 = pa0n, pa1 = pa1n, bv = bvn;
            if (it < 3) {
                const int off = (it + 1) * 16;
                pa0n = *(const float4*)(pa0row + off);
                pa1n = *(const float4*)(pa1row + off);
                bvn  = *(const float4*)(wbrow + off);
            }
            if (it) __syncthreads();
            As[lk + 0][lm] = f0 * pa0.x + f1 * pa1.x;
            As[lk + 1][lm] = f0 * pa0.y + f1 * pa1.y;
            As[lk + 2][lm] = f0 * pa0.z + f1 * pa1.z;
            As[lk + 3][lm] = f0 * pa0.w + f1 * pa1.w;
            Bs[lk + 0][lm] = bv.x; Bs[lk + 1][lm] = bv.y;
            Bs[lk + 2][lm] = bv.z; Bs[lk + 3][lm] = bv.w;
            __syncthreads();
#pragma unroll
            for (int kk = 0; kk < 16; kk++) {
                float4 a4 = *(float4*)&As[kk][ty * 4];
                float4 b4 = *(float4*)&Bs[kk][tx * 4];
                a00 += a4.x*b4.x; a01 += a4.x*b4.y; a02 += a4.x*b4.z; a03 += a4.x*b4.w;
                a10 += a4.y*b4.x; a11 += a4.y*b4.y; a12 += a4.y*b4.z; a13 += a4.y*b4.w;
                a20 += a4.z*b4.x; a21 += a4.z*b4.y; a22 += a4.z*b4.z; a23 += a4.z*b4.w;
                a30 += a4.w*b4.x; a31 += a4.w*b4.y; a32 += a4.w*b4.z; a33 += a4.w*b4.w;
            }
        }
        float* base = out + (size_t)(row0 + ty * 4) * Ss + col0 + tx * 4;
        atomicAdd(base + 0 * Ss + 0, a00); atomicAdd(base + 0 * Ss + 1, a01);
        atomicAdd(base + 0 * Ss + 2, a02); atomicAdd(base + 0 * Ss + 3, a03);
        atomicAdd(base + 1 * Ss + 0, a10); atomicAdd(base + 1 * Ss + 1, a11);
        atomicAdd(base + 1 * Ss + 2, a12); atomicAdd(base + 1 * Ss + 3, a13);
        atomicAdd(base + 2 * Ss + 0, a20); atomicAdd(base + 2 * Ss + 1, a21);
        atomicAdd(base + 2 * Ss + 2, a22); atomicAdd(base + 2 * Ss + 3, a23);
        atomicAdd(base + 3 * Ss + 0, a30); atomicAdd(base + 3 * Ss + 1, a31);
        atomicAdd(base + 3 * Ss + 2, a32); atomicAdd(base + 3 * Ss + 3, a33);
    }
}

// ---------------- launcher (1 graph node) ----------------
extern "C" void kernel_launch(void* const* d_in, const int* in_sizes, int n_in,
                              void* d_out, int out_size) {
    const float* in_state = (const float*)d_in[0];  // [B, S]
    const float* image    = (const float*)d_in[1];  // [B, D, N]
    const float* Wq       = (const float*)d_in[2];  // [D, S]
    const float* bq       = (const float*)d_in[3];  // [D]
    const float* Wc       = (const float*)d_in[4];  // [D, 2D]
    // d_in[5] = bc (cancels in softmax)
    const float* Wa       = (const float*)d_in[6];  // [1, D]
    // d_in[7] = ba (cancels in softmax)
    const float* Wo       = (const float*)d_in[8];  // [S, D]
    const float* bo       = (const float*)d_in[9];  // [S]
    float* out = (float*)d_out;                     // [B, S]

    fused_kernel<<<GRIDSZ, THREADS>>>(in_state, image, Wq, bq, Wa, Wc, Wo, bo, out);
}